// round 8
// baseline (speedup 1.0000x reference)
#include <cuda_runtime.h>
#include <cuda_bf16.h>
#include <math.h>
#include <stdint.h>

#define MAXN 50000
#define MAXE 600000
#define DIM  128
#define NGRAPH 64

// Scratch buffers (no cudaMalloc allowed)
__device__ __align__(16) float g_agg[MAXN * DIM];
__device__ __align__(16) float g_h  [MAXN * DIM];
__device__ int g_counts  [MAXN];
__device__ int g_rowstart[MAXN + 1];
__device__ int g_cursor  [MAXN];
__device__ int g_esorted [MAXE];
// Pre-converted tf32 hi/lo for the 6 layer weight matrices (each 128x128)
__device__ __align__(16) uint32_t g_whi[6 * 16384];
__device__ __align__(16) uint32_t g_wlo[6 * 16384];

// ---------------------------------------------------------------------------
// tf32 helpers
// ---------------------------------------------------------------------------
__device__ __forceinline__ uint32_t f2tf32(float f) {
    uint32_t r;
    asm("cvt.rna.tf32.f32 %0, %1;" : "=r"(r) : "f"(f));
    return r;
}
__device__ __forceinline__ void split2(float v, uint32_t& hi, uint32_t& lo) {
    hi = f2tf32(v);
    lo = f2tf32(v - __uint_as_float(hi));
}
__device__ __forceinline__ void mma_tf32(float d[4],
                                         const uint32_t a[4],
                                         const uint32_t b[2]) {
    asm volatile(
        "mma.sync.aligned.m16n8k8.row.col.f32.tf32.tf32.f32 "
        "{%0,%1,%2,%3}, {%4,%5,%6,%7}, {%8,%9}, {%0,%1,%2,%3};"
        : "+f"(d[0]), "+f"(d[1]), "+f"(d[2]), "+f"(d[3])
        : "r"(a[0]), "r"(a[1]), "r"(a[2]), "r"(a[3]),
          "r"(b[0]), "r"(b[1]));
}

// cp.async helpers
__device__ __forceinline__ uint32_t smem_u32(const void* p) {
    return (uint32_t)__cvta_generic_to_shared(p);
}
__device__ __forceinline__ void cpa16(uint32_t dst, const void* src, int srcsize) {
    asm volatile("cp.async.cg.shared.global [%0], [%1], 16, %2;"
                 :: "r"(dst), "l"(src), "r"(srcsize));
}
#define CP_COMMIT() asm volatile("cp.async.commit_group;")
#define CP_WAIT1()  asm volatile("cp.async.wait_group 1;")
#define CP_WAIT0()  asm volatile("cp.async.wait_group 0;")

// ---------------------------------------------------------------------------
// convert_w: split all 6 weight matrices into tf32 hi/lo (one-time per launch)
// ---------------------------------------------------------------------------
__global__ void convert_w(const float* __restrict__ w0, const float* __restrict__ w1,
                          const float* __restrict__ w2, const float* __restrict__ w3,
                          const float* __restrict__ w4, const float* __restrict__ w5,
                          uint32_t* __restrict__ hi, uint32_t* __restrict__ lo) {
    int i = blockIdx.x * 256 + threadIdx.x;      // 0 .. 6*16384-1
    int m = i >> 14;
    int off = i & 16383;
    const float* w = (m == 0) ? w0 : (m == 1) ? w1 : (m == 2) ? w2
                   : (m == 3) ? w3 : (m == 4) ? w4 : w5;
    float v = w[off];
    uint32_t h = f2tf32(v);
    hi[i] = h;
    lo[i] = f2tf32(v - __uint_as_float(h));
}

// ---------------------------------------------------------------------------
// CSR build
// ---------------------------------------------------------------------------
__global__ void hist_kernel(const int* __restrict__ ei, int* __restrict__ counts, int E) {
    int e = blockIdx.x * blockDim.x + threadIdx.x;
    if (e < E) atomicAdd(&counts[ei[E + e]], 1);
}

__global__ void __launch_bounds__(1024) scan_kernel(
    const int* __restrict__ counts, int* __restrict__ rowstart,
    int* __restrict__ cursor, int N)
{
    __shared__ int sums[1024];
    const int tid = threadIdx.x;
    const int chunk = (N + 1023) / 1024;
    const int lo = tid * chunk;
    const int hi = min(lo + chunk, N);

    int s = 0;
    for (int i = lo; i < hi; i++) s += counts[i];
    sums[tid] = s;
    __syncthreads();

    for (int d = 1; d < 1024; d <<= 1) {
        int v = (tid >= d) ? sums[tid - d] : 0;
        __syncthreads();
        sums[tid] += v;
        __syncthreads();
    }
    int run = (tid == 0) ? 0 : sums[tid - 1];
    for (int i = lo; i < hi; i++) {
        rowstart[i] = run;
        cursor[i]   = run;
        run += counts[i];
    }
    if (tid == 1023 && N > 0) rowstart[N] = run;
}

__global__ void fill_kernel(const int* __restrict__ ei, int* __restrict__ cursor,
                            int* __restrict__ esorted, int E) {
    int e = blockIdx.x * blockDim.x + threadIdx.x;
    if (e < E) {
        int dst = ei[E + e];
        int pos = atomicAdd(&cursor[dst], 1);
        esorted[pos] = ei[e];
    }
}

// ---------------------------------------------------------------------------
// gather: agg[n] = x[n] + sum_{s in in-neighbors(n)} x[s]
// ---------------------------------------------------------------------------
__global__ void __launch_bounds__(256) gather_kernel(
    const float4* __restrict__ x, const int* __restrict__ rowstart,
    const int* __restrict__ esorted, float4* __restrict__ agg, int N)
{
    int warp = (blockIdx.x * blockDim.x + threadIdx.x) >> 5;
    int lane = threadIdx.x & 31;
    if (warp >= N) return;
    int node  = warp;
    int start = __ldg(&rowstart[node]);
    int end   = __ldg(&rowstart[node + 1]);

    float4 acc = x[node * 32 + lane];
    float4 a1 = make_float4(0.f, 0.f, 0.f, 0.f);
    float4 a2 = make_float4(0.f, 0.f, 0.f, 0.f);
    float4 a3 = make_float4(0.f, 0.f, 0.f, 0.f);

    int i = start;
    for (; i + 3 < end; i += 4) {
        int s0 = __ldg(&esorted[i]);
        int s1 = __ldg(&esorted[i + 1]);
        int s2 = __ldg(&esorted[i + 2]);
        int s3 = __ldg(&esorted[i + 3]);
        float4 v0 = x[s0 * 32 + lane];
        float4 v1 = x[s1 * 32 + lane];
        float4 v2 = x[s2 * 32 + lane];
        float4 v3 = x[s3 * 32 + lane];
        acc.x += v0.x; acc.y += v0.y; acc.z += v0.z; acc.w += v0.w;
        a1.x += v1.x; a1.y += v1.y; a1.z += v1.z; a1.w += v1.w;
        a2.x += v2.x; a2.y += v2.y; a2.z += v2.z; a2.w += v2.w;
        a3.x += v3.x; a3.y += v3.y; a3.z += v3.z; a3.w += v3.w;
    }
    for (; i < end; i++) {
        int s = __ldg(&esorted[i]);
        float4 v = x[s * 32 + lane];
        acc.x += v.x; acc.y += v.y; acc.z += v.z; acc.w += v.w;
    }
    acc.x += a1.x + a2.x + a3.x;
    acc.y += a1.y + a2.y + a3.y;
    acc.z += a1.z + a2.z + a3.z;
    acc.w += a1.w + a2.w + a3.w;
    agg[node * 32 + lane] = acc;
}

// ---------------------------------------------------------------------------
// Fused, pipelined 2-GEMM MLP (3xTF32):
//   C = relu(relu(A@W1+b1)@W2+b2), 128-row tile per block.
//   K split into 8 chunks of 16; cp.async double-buffered loads overlap mma.
//   A (and smem-resident T) stored raw fp32, split to tf32 hi/lo at frag load.
// ---------------------------------------------------------------------------
#define AP 20        // A buffer pitch (f32)
#define WP 136       // W buffer pitch (u32)
#define TP 132       // T pitch (f32)
#define R0 16896     // region0 size in u32: max(T = 128*132, A db = 2*2560)
#define WBUF 4352    // per W buffer: hi 16*136 + lo 16*136
#define ABUF 2560    // per A buffer: 128*20 f32
#define MLP_SMEM ((R0 + 2 * WBUF) * 4)

// Copy A chunk kc (128 rows x 16 k, raw fp32) into Ab via cp.async
__device__ __forceinline__ void load_A_chunk(const float* A, int row0, int N,
                                             int kc, float* Ab, int tid) {
    #pragma unroll
    for (int i = 0; i < 2; i++) {
        int idx = tid + i * 256;          // 0..511
        int r  = idx >> 2;                // 0..127
        int c4 = idx & 3;                 // 0..3 (float4 within chunk)
        int g = row0 + r;
        const float4* src = ((const float4*)A) + ((long long)g * 32 + kc * 4 + c4);
        cpa16(smem_u32(&Ab[r * AP + c4 * 4]), src, (g < N) ? 16 : 0);
    }
}

// Copy W chunk kc (16 k-rows x 128 cols, hi+lo) into Wbuf via cp.async
__device__ __forceinline__ void load_W_chunk(const uint32_t* whi, const uint32_t* wlo,
                                             int kc, uint32_t* Wbuf, int tid) {
    #pragma unroll
    for (int i = 0; i < 2; i++) {
        int idx = tid + i * 256;          // 0..511
        int r = idx >> 5;                 // 0..15
        int c = idx & 31;                 // 16B group
        cpa16(smem_u32(&Wbuf[r * WP + c * 4]),        whi + (kc * 16 + r) * 128 + c * 4, 16);
        cpa16(smem_u32(&Wbuf[WBUF / 2 + r * WP + c * 4]), wlo + (kc * 16 + r) * 128 + c * 4, 16);
    }
}

// Compute one K=16 chunk: raw A (pitch P) split at load, W already tf32 hi/lo
template<int P>
__device__ __forceinline__ void compute_chunk(
    const float* Ab, const uint32_t* WbH, const uint32_t* WbL,
    float acc[4][4][4], int warpM, int warpN, int gid, int tig)
{
    #pragma unroll
    for (int ks = 0; ks < 2; ks++) {
        int k0 = ks * 8;
        uint32_t bH[4][2], bL[4][2];
        #pragma unroll
        for (int nt = 0; nt < 4; nt++) {
            int cb = warpN * 32 + nt * 8 + gid;
            bH[nt][0] = WbH[(k0 + tig) * WP + cb];
            bH[nt][1] = WbH[(k0 + tig + 4) * WP + cb];
            bL[nt][0] = WbL[(k0 + tig) * WP + cb];
            bL[nt][1] = WbL[(k0 + tig + 4) * WP + cb];
        }
        #pragma unroll
        for (int mt = 0; mt < 4; mt++) {
            int rb = warpM * 64 + mt * 16;
            float ar[4];
            ar[0] = Ab[(rb + gid) * P + k0 + tig];
            ar[1] = Ab[(rb + gid + 8) * P + k0 + tig];
            ar[2] = Ab[(rb + gid) * P + k0 + tig + 4];
            ar[3] = Ab[(rb + gid + 8) * P + k0 + tig + 4];
            uint32_t aH[4], aL[4];
            #pragma unroll
            for (int q = 0; q < 4; q++) split2(ar[q], aH[q], aL[q]);
            #pragma unroll
            for (int nt = 0; nt < 4; nt++) {
                mma_tf32(acc[mt][nt], aH, bH[nt]);
                mma_tf32(acc[mt][nt], aL, bH[nt]);
                mma_tf32(acc[mt][nt], aH, bL[nt]);
            }
        }
    }
}

__global__ void __launch_bounds__(256, 2) gin_mlp(
    const float* __restrict__ A,
    const uint32_t* __restrict__ w1hi, const uint32_t* __restrict__ w1lo,
    const float* __restrict__ b1,
    const uint32_t* __restrict__ w2hi, const uint32_t* __restrict__ w2lo,
    const float* __restrict__ b2,
    float* __restrict__ C, int N)
{
    extern __shared__ uint32_t sm[];
    float*    Araw = (float*)sm;            // phase 1: [2][ABUF]
    float*    Traw = (float*)sm;            // phases 2/3: [128][TP]
    uint32_t* Wb   = sm + R0;               // [2][WBUF]  (hi at +0, lo at +WBUF/2)

    const int tid   = threadIdx.x;
    const int lane  = tid & 31;
    const int warp  = tid >> 5;
    const int warpM = warp >> 2;
    const int warpN = warp & 3;
    const int gid   = lane >> 2;
    const int tig   = lane & 3;
    const int row0  = blockIdx.x * 128;

    float acc[4][4][4];
    #pragma unroll
    for (int i = 0; i < 4; i++)
        #pragma unroll
        for (int j = 0; j < 4; j++)
            #pragma unroll
            for (int k = 0; k < 4; k++) acc[i][j][k] = 0.f;

    // ================= Phase 1: T = A @ W1 (pipelined) =================
    load_A_chunk(A, row0, N, 0, Araw, tid);
    load_W_chunk(w1hi, w1lo, 0, Wb, tid);
    CP_COMMIT();

    for (int c = 0; c < 8; c++) {
        int cur = c & 1;
        if (c < 7) {
            int nxt = (c + 1) & 1;
            load_A_chunk(A, row0, N, c + 1, Araw + nxt * ABUF, tid);
            load_W_chunk(w1hi, w1lo, c + 1, Wb + nxt * WBUF, tid);
            CP_COMMIT();
            CP_WAIT1();
        } else {
            CP_WAIT0();
        }
        __syncthreads();
        compute_chunk<AP>(Araw + cur * ABUF,
                          Wb + cur * WBUF, Wb + cur * WBUF + WBUF / 2,
                          acc, warpM, warpN, gid, tig);
        __syncthreads();
    }

    // ========== Phase 2: T = relu(T + b1) -> smem (raw fp32) ==========
    // region1 is free now: prefetch W2 chunk 0 while we write T.
    load_W_chunk(w2hi, w2lo, 0, Wb, tid);
    CP_COMMIT();

    #pragma unroll
    for (int nt = 0; nt < 4; nt++) {
        int cb = warpN * 32 + nt * 8 + tig * 2;
        float2 bv = *(const float2*)&b1[cb];
        #pragma unroll
        for (int mt = 0; mt < 4; mt++) {
            int r0 = warpM * 64 + mt * 16 + gid;
            float2 o0, o1;
            o0.x = fmaxf(acc[mt][nt][0] + bv.x, 0.f);
            o0.y = fmaxf(acc[mt][nt][1] + bv.y, 0.f);
            o1.x = fmaxf(acc[mt][nt][2] + bv.x, 0.f);
            o1.y = fmaxf(acc[mt][nt][3] + bv.y, 0.f);
            *(float2*)&Traw[r0 * TP + cb]       = o0;
            *(float2*)&Traw[(r0 + 8) * TP + cb] = o1;
        }
    }
    #pragma unroll
    for (int i = 0; i < 4; i++)
        #pragma unroll
        for (int j = 0; j < 4; j++)
            #pragma unroll
            for (int k = 0; k < 4; k++) acc[i][j][k] = 0.f;
    __syncthreads();

    // ================= Phase 3: C = T @ W2 (pipelined) =================
    for (int c = 0; c < 8; c++) {
        int cur = c & 1;
        if (c < 7) {
            int nxt = (c + 1) & 1;
            load_W_chunk(w2hi, w2lo, c + 1, Wb + nxt * WBUF, tid);
            CP_COMMIT();
            CP_WAIT1();
        } else {
            CP_WAIT0();
        }
        __syncthreads();
        compute_chunk<TP>(Traw + c * 16,
                          Wb + cur * WBUF, Wb + cur * WBUF + WBUF / 2,
                          acc, warpM, warpN, gid, tig);
        __syncthreads();
    }

    // ================= Epilogue: relu(acc + b2) -> gmem =================
    #pragma unroll
    for (int nt = 0; nt < 4; nt++) {
        int cb = warpN * 32 + nt * 8;
        float2 bv = *(const float2*)&b2[cb + tig * 2];
        #pragma unroll
        for (int mt = 0; mt < 4; mt++) {
            int r0 = row0 + warpM * 64 + mt * 16 + gid;
            int r1 = r0 + 8;
            if (r0 < N) {
                float2 o;
                o.x = fmaxf(acc[mt][nt][0] + bv.x, 0.f);
                o.y = fmaxf(acc[mt][nt][1] + bv.y, 0.f);
                *(float2*)&C[(long long)r0 * DIM + cb + tig * 2] = o;
            }
            if (r1 < N) {
                float2 o;
                o.x = fmaxf(acc[mt][nt][2] + bv.x, 0.f);
                o.y = fmaxf(acc[mt][nt][3] + bv.y, 0.f);
                *(float2*)&C[(long long)r1 * DIM + cb + tig * 2] = o;
            }
        }
    }
}

// ---------------------------------------------------------------------------
// pool_ffn
// ---------------------------------------------------------------------------
__global__ void __launch_bounds__(256) pool_ffn(
    const float* __restrict__ h, const int* __restrict__ batch, int N,
    const float* __restrict__ wf1, const float* __restrict__ bf1,
    const float* __restrict__ wf2, const float* __restrict__ bf2,
    float* __restrict__ out)
{
    const int g    = blockIdx.x;
    const int tid  = threadIdx.x;
    const int f    = tid & 127;
    const int half = tid >> 7;

    int start, end;
    {
        int v = g;
        int lo = 0, hi = N;
        while (lo < hi) { int m = (lo + hi) >> 1; if (batch[m] < v) lo = m + 1; else hi = m; }
        start = lo;
        v = g + 1; lo = start; hi = N;
        while (lo < hi) { int m = (lo + hi) >> 1; if (batch[m] < v) lo = m + 1; else hi = m; }
        end = lo;
    }

    float a0 = 0.f, a1 = 0.f, a2 = 0.f, a3 = 0.f;
    int n = start + half;
    for (; n + 6 < end; n += 8) {
        a0 += h[(long long)(n    ) * DIM + f];
        a1 += h[(long long)(n + 2) * DIM + f];
        a2 += h[(long long)(n + 4) * DIM + f];
        a3 += h[(long long)(n + 6) * DIM + f];
    }
    for (; n < end; n += 2) a0 += h[(long long)n * DIM + f];
    float s = (a0 + a1) + (a2 + a3);

    __shared__ float ps[2][128];
    __shared__ float pooled_s[128];
    __shared__ float h1[128];
    __shared__ float o[10];

    ps[half][f] = s;
    __syncthreads();

    float cnt = fmaxf((float)(end - start), 1.0f);
    if (tid < 128) pooled_s[tid] = (ps[0][tid] + ps[1][tid]) / cnt;
    __syncthreads();

    if (tid < 128) {
        float acc = bf1[tid];
        #pragma unroll 8
        for (int k = 0; k < 128; k++) acc = fmaf(pooled_s[k], wf1[k * 128 + tid], acc);
        h1[tid] = fmaxf(acc, 0.f);
    }
    __syncthreads();

    if (tid < 10) {
        float acc = bf2[tid];
        #pragma unroll 8
        for (int k = 0; k < 128; k++) acc = fmaf(h1[k], wf2[k * 10 + tid], acc);
        o[tid] = acc;
    }
    __syncthreads();

    if (tid == 0) {
        float m = o[0];
        #pragma unroll
        for (int c = 1; c < 10; c++) m = fmaxf(m, o[c]);
        float e[10]; float sum = 0.f;
        #pragma unroll
        for (int c = 0; c < 10; c++) { e[c] = __expf(o[c] - m); sum += e[c]; }
        float inv = 1.f / sum;
        #pragma unroll
        for (int c = 0; c < 10; c++) out[g * 10 + c] = e[c] * inv;
    }
}

// ---------------------------------------------------------------------------
extern "C" void kernel_launch(void* const* d_in, const int* in_sizes, int n_in,
                              void* d_out, int out_size) {
    const float* x     = (const float*)d_in[0];
    const int*   ei    = (const int*)d_in[1];
    const int*   batch = (const int*)d_in[2];
    const float* w[6] = { (const float*)d_in[3],  (const float*)d_in[5],
                          (const float*)d_in[7],  (const float*)d_in[9],
                          (const float*)d_in[11], (const float*)d_in[13] };
    const float* b[6] = { (const float*)d_in[4],  (const float*)d_in[6],
                          (const float*)d_in[8],  (const float*)d_in[10],
                          (const float*)d_in[12], (const float*)d_in[14] };
    const float* wf1 = (const float*)d_in[15];
    const float* bf1 = (const float*)d_in[16];
    const float* wf2 = (const float*)d_in[17];
    const float* bf2 = (const float*)d_in[18];

    const int N = in_sizes[0] / DIM;
    const int E = in_sizes[1] / 2;

    float *agg, *hbuf;
    int *counts, *rowstart, *cursor, *esorted;
    uint32_t *whi, *wlo;
    cudaGetSymbolAddress((void**)&agg,      g_agg);
    cudaGetSymbolAddress((void**)&hbuf,     g_h);
    cudaGetSymbolAddress((void**)&counts,   g_counts);
    cudaGetSymbolAddress((void**)&rowstart, g_rowstart);
    cudaGetSymbolAddress((void**)&cursor,   g_cursor);
    cudaGetSymbolAddress((void**)&esorted,  g_esorted);
    cudaGetSymbolAddress((void**)&whi,      g_whi);
    cudaGetSymbolAddress((void**)&wlo,      g_wlo);

    static bool attr_set = false;
    if (!attr_set) {
        cudaFuncSetAttribute(gin_mlp,
                             cudaFuncAttributeMaxDynamicSharedMemorySize,
                             MLP_SMEM);
        attr_set = true;
    }

    // ---- one-time prep: weight conversion + CSR build ----
    convert_w<<<384, 256>>>(w[0], w[1], w[2], w[3], w[4], w[5], whi, wlo);
    cudaMemsetAsync(counts, 0, N * sizeof(int));
    const int eb = (E + 255) / 256;
    hist_kernel<<<eb, 256>>>(ei, counts, E);
    scan_kernel<<<1, 1024>>>(counts, rowstart, cursor, N);
    fill_kernel<<<eb, 256>>>(ei, cursor, esorted, E);

    const int gather_blocks = (N * 32 + 255) / 256;
    const int gemm_blocks = (N + 127) / 128;

    for (int L = 0; L < 3; L++) {
        const float* in = (L == 0) ? x : hbuf;
        gather_kernel<<<gather_blocks, 256>>>((const float4*)in, rowstart, esorted,
                                              (float4*)agg, N);
        gin_mlp<<<gemm_blocks, 256, MLP_SMEM>>>(
            agg,
            whi + (2 * L) * 16384,     wlo + (2 * L) * 16384,     b[2 * L],
            whi + (2 * L + 1) * 16384, wlo + (2 * L + 1) * 16384, b[2 * L + 1],
            hbuf, N);
    }
    pool_ffn<<<NGRAPH, 256>>>(hbuf, batch, N, wf1, bf1, wf2, bf2, (float*)d_out);
}

// round 9
// speedup vs baseline: 1.0056x; 1.0056x over previous
#include <cuda_runtime.h>
#include <cuda_bf16.h>
#include <math.h>
#include <stdint.h>

#define MAXN 50000
#define MAXE 600000
#define DIM  128
#define NGRAPH 64

// Scratch buffers (no cudaMalloc allowed)
__device__ __align__(16) float g_agg[MAXN * DIM];
__device__ __align__(16) float g_h  [MAXN * DIM];
__device__ int g_counts  [MAXN];
__device__ int g_rowstart[MAXN + 1];
__device__ int g_cursor  [MAXN];
__device__ int g_esorted [MAXE];
// Pre-converted tf32 hi/lo for the 6 layer weight matrices (each 128x128)
__device__ __align__(16) uint32_t g_whi[6 * 16384];
__device__ __align__(16) uint32_t g_wlo[6 * 16384];

// ---------------------------------------------------------------------------
// tf32 helpers
// ---------------------------------------------------------------------------
__device__ __forceinline__ uint32_t f2tf32(float f) {
    uint32_t r;
    asm("cvt.rna.tf32.f32 %0, %1;" : "=r"(r) : "f"(f));
    return r;
}
__device__ __forceinline__ void split2(float v, uint32_t& hi, uint32_t& lo) {
    hi = f2tf32(v);
    lo = f2tf32(v - __uint_as_float(hi));
}
__device__ __forceinline__ void mma_tf32(float d[4],
                                         const uint32_t a[4],
                                         const uint32_t b[2]) {
    asm volatile(
        "mma.sync.aligned.m16n8k8.row.col.f32.tf32.tf32.f32 "
        "{%0,%1,%2,%3}, {%4,%5,%6,%7}, {%8,%9}, {%0,%1,%2,%3};"
        : "+f"(d[0]), "+f"(d[1]), "+f"(d[2]), "+f"(d[3])
        : "r"(a[0]), "r"(a[1]), "r"(a[2]), "r"(a[3]),
          "r"(b[0]), "r"(b[1]));
}

// cp.async helpers
__device__ __forceinline__ uint32_t smem_u32(const void* p) {
    return (uint32_t)__cvta_generic_to_shared(p);
}
__device__ __forceinline__ void cpa16(uint32_t dst, const void* src, int srcsize) {
    asm volatile("cp.async.cg.shared.global [%0], [%1], 16, %2;"
                 :: "r"(dst), "l"(src), "r"(srcsize));
}
#define CP_COMMIT() asm volatile("cp.async.commit_group;")
#define CP_WAIT1()  asm volatile("cp.async.wait_group 1;")
#define CP_WAIT0()  asm volatile("cp.async.wait_group 0;")

// ---------------------------------------------------------------------------
// convert_w: split all 6 weight matrices into tf32 hi/lo (one-time per launch)
// ---------------------------------------------------------------------------
__global__ void convert_w(const float* __restrict__ w0, const float* __restrict__ w1,
                          const float* __restrict__ w2, const float* __restrict__ w3,
                          const float* __restrict__ w4, const float* __restrict__ w5,
                          uint32_t* __restrict__ hi, uint32_t* __restrict__ lo) {
    int i = blockIdx.x * 256 + threadIdx.x;      // 0 .. 6*16384-1
    int m = i >> 14;
    int off = i & 16383;
    const float* w = (m == 0) ? w0 : (m == 1) ? w1 : (m == 2) ? w2
                   : (m == 3) ? w3 : (m == 4) ? w4 : w5;
    float v = w[off];
    uint32_t h = f2tf32(v);
    hi[i] = h;
    lo[i] = f2tf32(v - __uint_as_float(h));
}

// ---------------------------------------------------------------------------
// CSR build
// ---------------------------------------------------------------------------
__global__ void hist_kernel(const int* __restrict__ ei, int* __restrict__ counts, int E) {
    int e = blockIdx.x * blockDim.x + threadIdx.x;
    if (e < E) atomicAdd(&counts[ei[E + e]], 1);
}

__global__ void __launch_bounds__(1024) scan_kernel(
    const int* __restrict__ counts, int* __restrict__ rowstart,
    int* __restrict__ cursor, int N)
{
    __shared__ int sums[1024];
    const int tid = threadIdx.x;
    const int chunk = (N + 1023) / 1024;
    const int lo = tid * chunk;
    const int hi = min(lo + chunk, N);

    int s = 0;
    for (int i = lo; i < hi; i++) s += counts[i];
    sums[tid] = s;
    __syncthreads();

    for (int d = 1; d < 1024; d <<= 1) {
        int v = (tid >= d) ? sums[tid - d] : 0;
        __syncthreads();
        sums[tid] += v;
        __syncthreads();
    }
    int run = (tid == 0) ? 0 : sums[tid - 1];
    for (int i = lo; i < hi; i++) {
        rowstart[i] = run;
        cursor[i]   = run;
        run += counts[i];
    }
    if (tid == 1023 && N > 0) rowstart[N] = run;
}

__global__ void fill_kernel(const int* __restrict__ ei, int* __restrict__ cursor,
                            int* __restrict__ esorted, int E) {
    int e = blockIdx.x * blockDim.x + threadIdx.x;
    if (e < E) {
        int dst = ei[E + e];
        int pos = atomicAdd(&cursor[dst], 1);
        esorted[pos] = ei[e];
    }
}

// ---------------------------------------------------------------------------
// gather: agg[n] = x[n] + sum_{s in in-neighbors(n)} x[s]
// ---------------------------------------------------------------------------
__global__ void __launch_bounds__(256) gather_kernel(
    const float4* __restrict__ x, const int* __restrict__ rowstart,
    const int* __restrict__ esorted, float4* __restrict__ agg, int N)
{
    int warp = (blockIdx.x * blockDim.x + threadIdx.x) >> 5;
    int lane = threadIdx.x & 31;
    if (warp >= N) return;
    int node  = warp;
    int start = __ldg(&rowstart[node]);
    int end   = __ldg(&rowstart[node + 1]);

    float4 acc = x[node * 32 + lane];
    float4 a1 = make_float4(0.f, 0.f, 0.f, 0.f);
    float4 a2 = make_float4(0.f, 0.f, 0.f, 0.f);
    float4 a3 = make_float4(0.f, 0.f, 0.f, 0.f);

    int i = start;
    for (; i + 3 < end; i += 4) {
        int s0 = __ldg(&esorted[i]);
        int s1 = __ldg(&esorted[i + 1]);
        int s2 = __ldg(&esorted[i + 2]);
        int s3 = __ldg(&esorted[i + 3]);
        float4 v0 = x[s0 * 32 + lane];
        float4 v1 = x[s1 * 32 + lane];
        float4 v2 = x[s2 * 32 + lane];
        float4 v3 = x[s3 * 32 + lane];
        acc.x += v0.x; acc.y += v0.y; acc.z += v0.z; acc.w += v0.w;
        a1.x += v1.x; a1.y += v1.y; a1.z += v1.z; a1.w += v1.w;
        a2.x += v2.x; a2.y += v2.y; a2.z += v2.z; a2.w += v2.w;
        a3.x += v3.x; a3.y += v3.y; a3.z += v3.z; a3.w += v3.w;
    }
    for (; i < end; i++) {
        int s = __ldg(&esorted[i]);
        float4 v = x[s * 32 + lane];
        acc.x += v.x; acc.y += v.y; acc.z += v.z; acc.w += v.w;
    }
    acc.x += a1.x + a2.x + a3.x;
    acc.y += a1.y + a2.y + a3.y;
    acc.z += a1.z + a2.z + a3.z;
    acc.w += a1.w + a2.w + a3.w;
    agg[node * 32 + lane] = acc;
}

// ---------------------------------------------------------------------------
// Fused, pipelined 2-GEMM MLP (3xTF32):
//   C = relu(relu(A@W1+b1)@W2+b2), 128-row tile per block.
//   K split into 8 chunks of 16; cp.async double-buffered loads overlap mma.
//   A (and smem-resident T) stored raw fp32, split to tf32 hi/lo at frag load.
// ---------------------------------------------------------------------------
#define AP 20        // A buffer pitch (f32)
#define WP 136       // W buffer pitch (u32)
#define TP 132       // T pitch (f32)
#define R0 16896     // region0 size in u32: max(T = 128*132, A db = 2*2560)
#define WBUF 4352    // per W buffer: hi 16*136 + lo 16*136
#define ABUF 2560    // per A buffer: 128*20 f32
#define MLP_SMEM ((R0 + 2 * WBUF) * 4)

// Copy A chunk kc (128 rows x 16 k, raw fp32) into Ab via cp.async
__device__ __forceinline__ void load_A_chunk(const float* A, int row0, int N,
                                             int kc, float* Ab, int tid) {
    #pragma unroll
    for (int i = 0; i < 2; i++) {
        int idx = tid + i * 256;          // 0..511
        int r  = idx >> 2;                // 0..127
        int c4 = idx & 3;                 // 0..3 (float4 within chunk)
        int g = row0 + r;
        const float4* src = ((const float4*)A) + ((long long)g * 32 + kc * 4 + c4);
        cpa16(smem_u32(&Ab[r * AP + c4 * 4]), src, (g < N) ? 16 : 0);
    }
}

// Copy W chunk kc (16 k-rows x 128 cols, hi+lo) into Wbuf via cp.async
__device__ __forceinline__ void load_W_chunk(const uint32_t* whi, const uint32_t* wlo,
                                             int kc, uint32_t* Wbuf, int tid) {
    #pragma unroll
    for (int i = 0; i < 2; i++) {
        int idx = tid + i * 256;          // 0..511
        int r = idx >> 5;                 // 0..15
        int c = idx & 31;                 // 16B group
        cpa16(smem_u32(&Wbuf[r * WP + c * 4]),        whi + (kc * 16 + r) * 128 + c * 4, 16);
        cpa16(smem_u32(&Wbuf[WBUF / 2 + r * WP + c * 4]), wlo + (kc * 16 + r) * 128 + c * 4, 16);
    }
}

// Compute one K=16 chunk: raw A (pitch P) split at load, W already tf32 hi/lo
template<int P>
__device__ __forceinline__ void compute_chunk(
    const float* Ab, const uint32_t* WbH, const uint32_t* WbL,
    float acc[4][4][4], int warpM, int warpN, int gid, int tig)
{
    #pragma unroll
    for (int ks = 0; ks < 2; ks++) {
        int k0 = ks * 8;
        uint32_t bH[4][2], bL[4][2];
        #pragma unroll
        for (int nt = 0; nt < 4; nt++) {
            int cb = warpN * 32 + nt * 8 + gid;
            bH[nt][0] = WbH[(k0 + tig) * WP + cb];
            bH[nt][1] = WbH[(k0 + tig + 4) * WP + cb];
            bL[nt][0] = WbL[(k0 + tig) * WP + cb];
            bL[nt][1] = WbL[(k0 + tig + 4) * WP + cb];
        }
        #pragma unroll
        for (int mt = 0; mt < 4; mt++) {
            int rb = warpM * 64 + mt * 16;
            float ar[4];
            ar[0] = Ab[(rb + gid) * P + k0 + tig];
            ar[1] = Ab[(rb + gid + 8) * P + k0 + tig];
            ar[2] = Ab[(rb + gid) * P + k0 + tig + 4];
            ar[3] = Ab[(rb + gid + 8) * P + k0 + tig + 4];
            uint32_t aH[4], aL[4];
            #pragma unroll
            for (int q = 0; q < 4; q++) split2(ar[q], aH[q], aL[q]);
            #pragma unroll
            for (int nt = 0; nt < 4; nt++) {
                mma_tf32(acc[mt][nt], aH, bH[nt]);
                mma_tf32(acc[mt][nt], aL, bH[nt]);
                mma_tf32(acc[mt][nt], aH, bL[nt]);
            }
        }
    }
}

__global__ void __launch_bounds__(256, 2) gin_mlp(
    const float* __restrict__ A,
    const uint32_t* __restrict__ w1hi, const uint32_t* __restrict__ w1lo,
    const float* __restrict__ b1,
    const uint32_t* __restrict__ w2hi, const uint32_t* __restrict__ w2lo,
    const float* __restrict__ b2,
    float* __restrict__ C, int N)
{
    extern __shared__ uint32_t sm[];
    float*    Araw = (float*)sm;            // phase 1: [2][ABUF]
    float*    Traw = (float*)sm;            // phases 2/3: [128][TP]
    uint32_t* Wb   = sm + R0;               // [2][WBUF]  (hi at +0, lo at +WBUF/2)

    const int tid   = threadIdx.x;
    const int lane  = tid & 31;
    const int warp  = tid >> 5;
    const int warpM = warp >> 2;
    const int warpN = warp & 3;
    const int gid   = lane >> 2;
    const int tig   = lane & 3;
    const int row0  = blockIdx.x * 128;

    float acc[4][4][4];
    #pragma unroll
    for (int i = 0; i < 4; i++)
        #pragma unroll
        for (int j = 0; j < 4; j++)
            #pragma unroll
            for (int k = 0; k < 4; k++) acc[i][j][k] = 0.f;

    // ================= Phase 1: T = A @ W1 (pipelined) =================
    load_A_chunk(A, row0, N, 0, Araw, tid);
    load_W_chunk(w1hi, w1lo, 0, Wb, tid);
    CP_COMMIT();

    for (int c = 0; c < 8; c++) {
        int cur = c & 1;
        if (c < 7) {
            int nxt = (c + 1) & 1;
            load_A_chunk(A, row0, N, c + 1, Araw + nxt * ABUF, tid);
            load_W_chunk(w1hi, w1lo, c + 1, Wb + nxt * WBUF, tid);
            CP_COMMIT();
            CP_WAIT1();
        } else {
            CP_WAIT0();
        }
        __syncthreads();
        compute_chunk<AP>(Araw + cur * ABUF,
                          Wb + cur * WBUF, Wb + cur * WBUF + WBUF / 2,
                          acc, warpM, warpN, gid, tig);
        __syncthreads();
    }

    // ========== Phase 2: T = relu(T + b1) -> smem (raw fp32) ==========
    // region1 is free now: prefetch W2 chunk 0 while we write T.
    load_W_chunk(w2hi, w2lo, 0, Wb, tid);
    CP_COMMIT();

    #pragma unroll
    for (int nt = 0; nt < 4; nt++) {
        int cb = warpN * 32 + nt * 8 + tig * 2;
        float2 bv = *(const float2*)&b1[cb];
        #pragma unroll
        for (int mt = 0; mt < 4; mt++) {
            int r0 = warpM * 64 + mt * 16 + gid;
            float2 o0, o1;
            o0.x = fmaxf(acc[mt][nt][0] + bv.x, 0.f);
            o0.y = fmaxf(acc[mt][nt][1] + bv.y, 0.f);
            o1.x = fmaxf(acc[mt][nt][2] + bv.x, 0.f);
            o1.y = fmaxf(acc[mt][nt][3] + bv.y, 0.f);
            *(float2*)&Traw[r0 * TP + cb]       = o0;
            *(float2*)&Traw[(r0 + 8) * TP + cb] = o1;
        }
    }
    #pragma unroll
    for (int i = 0; i < 4; i++)
        #pragma unroll
        for (int j = 0; j < 4; j++)
            #pragma unroll
            for (int k = 0; k < 4; k++) acc[i][j][k] = 0.f;
    __syncthreads();

    // ================= Phase 3: C = T @ W2 (pipelined) =================
    for (int c = 0; c < 8; c++) {
        int cur = c & 1;
        if (c < 7) {
            int nxt = (c + 1) & 1;
            load_W_chunk(w2hi, w2lo, c + 1, Wb + nxt * WBUF, tid);
            CP_COMMIT();
            CP_WAIT1();
        } else {
            CP_WAIT0();
        }
        __syncthreads();
        compute_chunk<TP>(Traw + c * 16,
                          Wb + cur * WBUF, Wb + cur * WBUF + WBUF / 2,
                          acc, warpM, warpN, gid, tig);
        __syncthreads();
    }

    // ================= Epilogue: relu(acc + b2) -> gmem =================
    #pragma unroll
    for (int nt = 0; nt < 4; nt++) {
        int cb = warpN * 32 + nt * 8;
        float2 bv = *(const float2*)&b2[cb + tig * 2];
        #pragma unroll
        for (int mt = 0; mt < 4; mt++) {
            int r0 = row0 + warpM * 64 + mt * 16 + gid;
            int r1 = r0 + 8;
            if (r0 < N) {
                float2 o;
                o.x = fmaxf(acc[mt][nt][0] + bv.x, 0.f);
                o.y = fmaxf(acc[mt][nt][1] + bv.y, 0.f);
                *(float2*)&C[(long long)r0 * DIM + cb + tig * 2] = o;
            }
            if (r1 < N) {
                float2 o;
                o.x = fmaxf(acc[mt][nt][2] + bv.x, 0.f);
                o.y = fmaxf(acc[mt][nt][3] + bv.y, 0.f);
                *(float2*)&C[(long long)r1 * DIM + cb + tig * 2] = o;
            }
        }
    }
}

// ---------------------------------------------------------------------------
// pool_ffn
// ---------------------------------------------------------------------------
__global__ void __launch_bounds__(256) pool_ffn(
    const float* __restrict__ h, const int* __restrict__ batch, int N,
    const float* __restrict__ wf1, const float* __restrict__ bf1,
    const float* __restrict__ wf2, const float* __restrict__ bf2,
    float* __restrict__ out)
{
    const int g    = blockIdx.x;
    const int tid  = threadIdx.x;
    const int f    = tid & 127;
    const int half = tid >> 7;

    int start, end;
    {
        int v = g;
        int lo = 0, hi = N;
        while (lo < hi) { int m = (lo + hi) >> 1; if (batch[m] < v) lo = m + 1; else hi = m; }
        start = lo;
        v = g + 1; lo = start; hi = N;
        while (lo < hi) { int m = (lo + hi) >> 1; if (batch[m] < v) lo = m + 1; else hi = m; }
        end = lo;
    }

    float a0 = 0.f, a1 = 0.f, a2 = 0.f, a3 = 0.f;
    int n = start + half;
    for (; n + 6 < end; n += 8) {
        a0 += h[(long long)(n    ) * DIM + f];
        a1 += h[(long long)(n + 2) * DIM + f];
        a2 += h[(long long)(n + 4) * DIM + f];
        a3 += h[(long long)(n + 6) * DIM + f];
    }
    for (; n < end; n += 2) a0 += h[(long long)n * DIM + f];
    float s = (a0 + a1) + (a2 + a3);

    __shared__ float ps[2][128];
    __shared__ float pooled_s[128];
    __shared__ float h1[128];
    __shared__ float o[10];

    ps[half][f] = s;
    __syncthreads();

    float cnt = fmaxf((float)(end - start), 1.0f);
    if (tid < 128) pooled_s[tid] = (ps[0][tid] + ps[1][tid]) / cnt;
    __syncthreads();

    if (tid < 128) {
        float acc = bf1[tid];
        #pragma unroll 8
        for (int k = 0; k < 128; k++) acc = fmaf(pooled_s[k], wf1[k * 128 + tid], acc);
        h1[tid] = fmaxf(acc, 0.f);
    }
    __syncthreads();

    if (tid < 10) {
        float acc = bf2[tid];
        #pragma unroll 8
        for (int k = 0; k < 128; k++) acc = fmaf(h1[k], wf2[k * 10 + tid], acc);
        o[tid] = acc;
    }
    __syncthreads();

    if (tid == 0) {
        float m = o[0];
        #pragma unroll
        for (int c = 1; c < 10; c++) m = fmaxf(m, o[c]);
        float e[10]; float sum = 0.f;
        #pragma unroll
        for (int c = 0; c < 10; c++) { e[c] = __expf(o[c] - m); sum += e[c]; }
        float inv = 1.f / sum;
        #pragma unroll
        for (int c = 0; c < 10; c++) out[g * 10 + c] = e[c] * inv;
    }
}

// ---------------------------------------------------------------------------
extern "C" void kernel_launch(void* const* d_in, const int* in_sizes, int n_in,
                              void* d_out, int out_size) {
    const float* x     = (const float*)d_in[0];
    const int*   ei    = (const int*)d_in[1];
    const int*   batch = (const int*)d_in[2];
    const float* w[6] = { (const float*)d_in[3],  (const float*)d_in[5],
                          (const float*)d_in[7],  (const float*)d_in[9],
                          (const float*)d_in[11], (const float*)d_in[13] };
    const float* b[6] = { (const float*)d_in[4],  (const float*)d_in[6],
                          (const float*)d_in[8],  (const float*)d_in[10],
                          (const float*)d_in[12], (const float*)d_in[14] };
    const float* wf1 = (const float*)d_in[15];
    const float* bf1 = (const float*)d_in[16];
    const float* wf2 = (const float*)d_in[17];
    const float* bf2 = (const float*)d_in[18];

    const int N = in_sizes[0] / DIM;
    const int E = in_sizes[1] / 2;

    float *agg, *hbuf;
    int *counts, *rowstart, *cursor, *esorted;
    uint32_t *whi, *wlo;
    cudaGetSymbolAddress((void**)&agg,      g_agg);
    cudaGetSymbolAddress((void**)&hbuf,     g_h);
    cudaGetSymbolAddress((void**)&counts,   g_counts);
    cudaGetSymbolAddress((void**)&rowstart, g_rowstart);
    cudaGetSymbolAddress((void**)&cursor,   g_cursor);
    cudaGetSymbolAddress((void**)&esorted,  g_esorted);
    cudaGetSymbolAddress((void**)&whi,      g_whi);
    cudaGetSymbolAddress((void**)&wlo,      g_wlo);

    static bool attr_set = false;
    if (!attr_set) {
        cudaFuncSetAttribute(gin_mlp,
                             cudaFuncAttributeMaxDynamicSharedMemorySize,
                             MLP_SMEM);
        attr_set = true;
    }

    // ---- one-time prep: weight conversion + CSR build ----
    convert_w<<<384, 256>>>(w[0], w[1], w[2], w[3], w[4], w[5], whi, wlo);
    cudaMemsetAsync(counts, 0, N * sizeof(int));
    const int eb = (E + 255) / 256;
    hist_kernel<<<eb, 256>>>(ei, counts, E);
    scan_kernel<<<1, 1024>>>(counts, rowstart, cursor, N);
    fill_kernel<<<eb, 256>>>(ei, cursor, esorted, E);

    const int gather_blocks = (N * 32 + 255) / 256;
    const int gemm_blocks = (N + 127) / 128;

    for (int L = 0; L < 3; L++) {
        const float* in = (L == 0) ? x : hbuf;
        gather_kernel<<<gather_blocks, 256>>>((const float4*)in, rowstart, esorted,
                                              (float4*)agg, N);
        gin_mlp<<<gemm_blocks, 256, MLP_SMEM>>>(
            agg,
            whi + (2 * L) * 16384,     wlo + (2 * L) * 16384,     b[2 * L],
            whi + (2 * L + 1) * 16384, wlo + (2 * L + 1) * 16384, b[2 * L + 1],
            hbuf, N);
    }
    pool_ffn<<<NGRAPH, 256>>>(hbuf, batch, N, wf1, bf1, wf2, bf2, (float*)d_out);
}